// round 1
// baseline (speedup 1.0000x reference)
#include <cuda_runtime.h>

#define Dv 128
#define Hv 128
#define Wv 128
#define NS 16
#define HS 128
#define WS 128
#define KK 27
#define NITER 10
#define VOLN (Dv*Hv*Wv)
#define SLN (NS*HS*WS)
#define HW (Hv*Wv)

// ---- scratch (no allocations allowed) ----
__device__ float g_x[VOLN];
__device__ float g_r[VOLN];
__device__ float g_p[VOLN];
__device__ float g_Ap[VOLN];
__device__ float g_b[VOLN];
__device__ float g_s[SLN];
__device__ double g_scal[64];   // [0..10]=rr_i, [32..41]=pAp_i, [63]=dummy

// ---------------------------------------------------------------------------
__device__ __forceinline__ void block_reduce_add(double v, double* target) {
    #pragma unroll
    for (int o = 16; o > 0; o >>= 1) v += __shfl_down_sync(0xffffffffu, v, o);
    __shared__ double sm[32];
    int lane = threadIdx.x & 31, w = threadIdx.x >> 5;
    if (lane == 0) sm[w] = v;
    __syncthreads();
    if (w == 0) {
        v = (lane < (int)(blockDim.x >> 5)) ? sm[lane] : 0.0;
        #pragma unroll
        for (int o = 16; o > 0; o >>= 1) v += __shfl_down_sync(0xffffffffu, v, o);
        if (lane == 0) atomicAdd(target, v);
    }
}

// Shared per-slice setup: R (3x3), t+center, rotated PSF offsets, psf weights.
#define SLICE_SHARED_DECL \
    __shared__ float sR[9]; __shared__ float st[3]; \
    __shared__ float sox[KK]; __shared__ float soy[KK]; __shared__ float soz[KK]; \
    __shared__ float spsf[KK];

__device__ __forceinline__ void slice_setup(const float* __restrict__ theta,
                                            const float* __restrict__ psf, int n,
                                            float* sR, float* st,
                                            float* sox, float* soy, float* soz,
                                            float* spsf) {
    int tid = threadIdx.x;
    if (tid < 9)       sR[tid]    = theta[n*12 + (tid/3)*4 + (tid%3)];
    else if (tid < 12) st[tid-9]  = theta[n*12 + (tid-9)*4 + 3] + 63.5f;
    __syncthreads();
    if (tid < KK) {
        float ox = (float)(tid % 3) - 1.f;
        float oy = (float)((tid / 3) % 3) - 1.f;
        float oz = (float)(tid / 9) - 1.f;
        sox[tid] = sR[0]*ox + sR[1]*oy + sR[2]*oz;
        soy[tid] = sR[3]*ox + sR[4]*oy + sR[5]*oz;
        soz[tid] = sR[6]*ox + sR[7]*oy + sR[8]*oz;
        spsf[tid] = psf[tid];
    }
    __syncthreads();
}

// ---------------------------------------------------------------------------
// A: PSF-weighted trilinear gather vol -> slices. Also accumulates ||s||^2
// (== p^T AtA p when vol==p) into ssq.
__global__ void A_kernel(const float* __restrict__ theta, const float* __restrict__ psf,
                         const float* __restrict__ vol, float* __restrict__ sout,
                         double* __restrict__ ssq) {
    SLICE_SHARED_DECL
    const int n = blockIdx.y;
    slice_setup(theta, psf, n, sR, st, sox, soy, soz, spsf);

    int pix = blockIdx.x * blockDim.x + threadIdx.x;
    int iw = pix & (WS - 1);
    int ih = pix >> 7;
    float fu = ((float)iw - 63.5f) * 1.5f;
    float fv = ((float)ih - 63.5f) * 1.5f;
    float qx = sR[0]*fu + sR[1]*fv + st[0];
    float qy = sR[3]*fu + sR[4]*fv + st[1];
    float qz = sR[6]*fu + sR[7]*fv + st[2];

    float acc = 0.f;
    for (int k = 0; k < KK; k++) {
        float px = qx + sox[k], py = qy + soy[k], pz = qz + soz[k];
        float xf = floorf(px), yf = floorf(py), zf = floorf(pz);
        int ix = (int)xf, iy = (int)yf, iz = (int)zf;
        float fx = px - xf, fy = py - yf, fz = pz - zf;
        float val;
        if (((unsigned)ix < Wv-1u) && ((unsigned)iy < Hv-1u) && ((unsigned)iz < Dv-1u)) {
            const float* b0 = vol + ((iz*Hv + iy)*Wv + ix);
            float v000 = __ldg(b0),        v001 = __ldg(b0+1);
            float v010 = __ldg(b0+Wv),     v011 = __ldg(b0+Wv+1);
            float v100 = __ldg(b0+HW),     v101 = __ldg(b0+HW+1);
            float v110 = __ldg(b0+HW+Wv),  v111 = __ldg(b0+HW+Wv+1);
            float c00 = v000 + fx*(v001 - v000);
            float c01 = v010 + fx*(v011 - v010);
            float c10 = v100 + fx*(v101 - v100);
            float c11 = v110 + fx*(v111 - v110);
            float c0 = c00 + fy*(c01 - c00);
            float c1 = c10 + fy*(c11 - c10);
            val = c0 + fz*(c1 - c0);
        } else {
            float wx[2] = {1.f - fx, fx}, wy[2] = {1.f - fy, fy}, wz[2] = {1.f - fz, fz};
            val = 0.f;
            #pragma unroll
            for (int dz = 0; dz < 2; dz++)
            #pragma unroll
            for (int dy = 0; dy < 2; dy++)
            #pragma unroll
            for (int dx = 0; dx < 2; dx++) {
                int xx = ix + dx, yy = iy + dy, zz = iz + dz;
                if (((unsigned)xx < (unsigned)Wv) && ((unsigned)yy < (unsigned)Hv) &&
                    ((unsigned)zz < (unsigned)Dv))
                    val += wx[dx]*wy[dy]*wz[dz]*__ldg(vol + ((zz*Hv + yy)*Wv + xx));
            }
        }
        acc += spsf[k] * val;
    }
    sout[n*(HS*WS) + pix] = acc;
    block_reduce_add((double)acc * (double)acc, ssq);
}

// ---------------------------------------------------------------------------
// At: PSF-weighted trilinear scatter-add slices -> volume (volout must be zeroed).
__global__ void At_kernel(const float* __restrict__ theta, const float* __restrict__ psf,
                          const float* __restrict__ sl, float* __restrict__ volout) {
    SLICE_SHARED_DECL
    const int n = blockIdx.y;
    slice_setup(theta, psf, n, sR, st, sox, soy, soz, spsf);

    int pix = blockIdx.x * blockDim.x + threadIdx.x;
    int iw = pix & (WS - 1);
    int ih = pix >> 7;
    float fu = ((float)iw - 63.5f) * 1.5f;
    float fv = ((float)ih - 63.5f) * 1.5f;
    float qx = sR[0]*fu + sR[1]*fv + st[0];
    float qy = sR[3]*fu + sR[4]*fv + st[1];
    float qz = sR[6]*fu + sR[7]*fv + st[2];
    float v = sl[n*(HS*WS) + pix];

    for (int k = 0; k < KK; k++) {
        float wv = v * spsf[k];
        float px = qx + sox[k], py = qy + soy[k], pz = qz + soz[k];
        float xf = floorf(px), yf = floorf(py), zf = floorf(pz);
        int ix = (int)xf, iy = (int)yf, iz = (int)zf;
        float fx = px - xf, fy = py - yf, fz = pz - zf;
        if (((unsigned)ix < Wv-1u) && ((unsigned)iy < Hv-1u) && ((unsigned)iz < Dv-1u)) {
            float* b0 = volout + ((iz*Hv + iy)*Wv + ix);
            float wx1 = fx, wx0 = 1.f - fx;
            float wy0 = 1.f - fy, wy1 = fy;
            float wz0 = 1.f - fz, wz1 = fz;
            float w00 = wy0*wz0*wv, w10 = wy1*wz0*wv;
            float w01 = wy0*wz1*wv, w11 = wy1*wz1*wv;
            atomicAdd(b0,         wx0*w00); atomicAdd(b0+1,        wx1*w00);
            atomicAdd(b0+Wv,      wx0*w10); atomicAdd(b0+Wv+1,     wx1*w10);
            atomicAdd(b0+HW,      wx0*w01); atomicAdd(b0+HW+1,     wx1*w01);
            atomicAdd(b0+HW+Wv,   wx0*w11); atomicAdd(b0+HW+Wv+1,  wx1*w11);
        } else {
            float wx[2] = {1.f - fx, fx}, wy[2] = {1.f - fy, fy}, wz[2] = {1.f - fz, fz};
            #pragma unroll
            for (int dz = 0; dz < 2; dz++)
            #pragma unroll
            for (int dy = 0; dy < 2; dy++)
            #pragma unroll
            for (int dx = 0; dx < 2; dx++) {
                int xx = ix + dx, yy = iy + dy, zz = iz + dz;
                if (((unsigned)xx < (unsigned)Wv) && ((unsigned)yy < (unsigned)Hv) &&
                    ((unsigned)zz < (unsigned)Dv))
                    atomicAdd(volout + ((zz*Hv + yy)*Wv + xx), wx[dx]*wy[dy]*wz[dz]*wv);
            }
        }
    }
}

// ---------------------------------------------------------------------------
// r = b - Ap; p = r; rr += ||r||^2
__global__ void resid_init_kernel(const float4* __restrict__ b, const float4* __restrict__ Ap,
                                  float4* __restrict__ r, float4* __restrict__ p,
                                  double* __restrict__ rr) {
    int i = blockIdx.x * blockDim.x + threadIdx.x;
    float4 bv = b[i], av = Ap[i];
    float4 rv = make_float4(bv.x - av.x, bv.y - av.y, bv.z - av.z, bv.w - av.w);
    r[i] = rv; p[i] = rv;
    double s = (double)rv.x*rv.x + (double)rv.y*rv.y + (double)rv.z*rv.z + (double)rv.w*rv.w;
    block_reduce_add(s, rr);
}

// alpha = rr_old/pAp; x += alpha p; r -= alpha Ap; rr_new += ||r||^2; optional relu out
__global__ void xr_update_kernel(float4* __restrict__ x, float4* __restrict__ r,
                                 const float4* __restrict__ p, const float4* __restrict__ Ap,
                                 const double* __restrict__ rr_old, const double* __restrict__ pAp,
                                 double* __restrict__ rr_new, float4* __restrict__ out) {
    int i = blockIdx.x * blockDim.x + threadIdx.x;
    float alpha = (float)(*rr_old / *pAp);
    float4 xv = x[i], pv = p[i], rv = r[i], av = Ap[i];
    xv.x += alpha*pv.x; xv.y += alpha*pv.y; xv.z += alpha*pv.z; xv.w += alpha*pv.w;
    rv.x -= alpha*av.x; rv.y -= alpha*av.y; rv.z -= alpha*av.z; rv.w -= alpha*av.w;
    x[i] = xv; r[i] = rv;
    if (out) {
        float4 ov = make_float4(fmaxf(xv.x, 0.f), fmaxf(xv.y, 0.f),
                                fmaxf(xv.z, 0.f), fmaxf(xv.w, 0.f));
        out[i] = ov;
    }
    double s = (double)rv.x*rv.x + (double)rv.y*rv.y + (double)rv.z*rv.z + (double)rv.w*rv.w;
    block_reduce_add(s, rr_new);
}

// p = r + beta p, beta = rr_new/rr_old
__global__ void p_update_kernel(float4* __restrict__ p, const float4* __restrict__ r,
                                const double* __restrict__ rr_new,
                                const double* __restrict__ rr_old) {
    int i = blockIdx.x * blockDim.x + threadIdx.x;
    float beta = (float)(*rr_new / *rr_old);
    float4 pv = p[i], rv = r[i];
    pv.x = rv.x + beta*pv.x; pv.y = rv.y + beta*pv.y;
    pv.z = rv.z + beta*pv.z; pv.w = rv.w + beta*pv.w;
    p[i] = pv;
}

// ---------------------------------------------------------------------------
extern "C" void kernel_launch(void* const* d_in, const int* in_sizes, int n_in,
                              void* d_out, int out_size) {
    (void)in_sizes; (void)n_in; (void)out_size;
    const float* theta  = (const float*)d_in[0];
    const float* slices = (const float*)d_in[1];
    const float* volume = (const float*)d_in[2];
    const float* psf    = (const float*)d_in[3];
    float* out = (float*)d_out;

    void *vx, *vr, *vp, *vAp, *vb, *vs, *vsc;
    cudaGetSymbolAddress(&vx, g_x);
    cudaGetSymbolAddress(&vr, g_r);
    cudaGetSymbolAddress(&vp, g_p);
    cudaGetSymbolAddress(&vAp, g_Ap);
    cudaGetSymbolAddress(&vb, g_b);
    cudaGetSymbolAddress(&vs, g_s);
    cudaGetSymbolAddress(&vsc, g_scal);
    float *gx = (float*)vx, *gr = (float*)vr, *gp = (float*)vp;
    float *gAp = (float*)vAp, *gb = (float*)vb, *gs = (float*)vs;
    double* gsc = (double*)vsc;

    const dim3 gridS(HS*WS/256, NS);
    const int vgrid = VOLN/4/256;

    cudaMemsetAsync(gsc, 0, 64*sizeof(double), 0);
    cudaMemsetAsync(gb, 0, VOLN*sizeof(float), 0);
    cudaMemcpyAsync(gx, volume, VOLN*sizeof(float), cudaMemcpyDeviceToDevice, 0);

    // b = At(slices)
    At_kernel<<<gridS, 256>>>(theta, psf, slices, gb);

    // r0 = b - AtA(x0); p = r0; rr0
    A_kernel<<<gridS, 256>>>(theta, psf, gx, gs, gsc + 63);
    cudaMemsetAsync(gAp, 0, VOLN*sizeof(float), 0);
    At_kernel<<<gridS, 256>>>(theta, psf, gs, gAp);
    resid_init_kernel<<<vgrid, 256>>>((const float4*)gb, (const float4*)gAp,
                                      (float4*)gr, (float4*)gp, gsc + 0);

    for (int i = 0; i < NITER; i++) {
        // s = A(p), pAp = ||s||^2 (AtA symmetry)
        A_kernel<<<gridS, 256>>>(theta, psf, gp, gs, gsc + 32 + i);
        cudaMemsetAsync(gAp, 0, VOLN*sizeof(float), 0);
        At_kernel<<<gridS, 256>>>(theta, psf, gs, gAp);
        xr_update_kernel<<<vgrid, 256>>>((float4*)gx, (float4*)gr,
                                         (const float4*)gp, (const float4*)gAp,
                                         gsc + i, gsc + 32 + i, gsc + i + 1,
                                         (i == NITER-1) ? (float4*)out : nullptr);
        if (i < NITER-1)
            p_update_kernel<<<vgrid, 256>>>((float4*)gp, (const float4*)gr,
                                            gsc + i + 1, gsc + i);
    }
}

// round 2
// speedup vs baseline: 1.0073x; 1.0073x over previous
#include <cuda_runtime.h>

#define Dv 128
#define Hv 128
#define Wv 128
#define NS 16
#define HS 128
#define WS 128
#define KK 27
#define NITER 10
#define VOLN (Dv*Hv*Wv)
#define SLN (NS*HS*WS)
#define HW (Hv*Wv)

// ---- scratch (no allocations allowed) ----
__device__ float g_x[VOLN];
__device__ float g_r[VOLN];
__device__ float g_p[VOLN];
__device__ float g_s[SLN];
__device__ double g_scal[64];   // [0..10]=rr_i, [32..41]=pAp_i, [63]=dummy

// ---------------------------------------------------------------------------
__device__ __forceinline__ void block_reduce_add(double v, double* target) {
    #pragma unroll
    for (int o = 16; o > 0; o >>= 1) v += __shfl_down_sync(0xffffffffu, v, o);
    __shared__ double sm[32];
    int lane = threadIdx.x & 31, w = threadIdx.x >> 5;
    if (lane == 0) sm[w] = v;
    __syncthreads();
    if (w == 0) {
        v = (lane < (int)(blockDim.x >> 5)) ? sm[lane] : 0.0;
        #pragma unroll
        for (int o = 16; o > 0; o >>= 1) v += __shfl_down_sync(0xffffffffu, v, o);
        if (lane == 0) atomicAdd(target, v);
    }
}

// Shared per-slice setup: R (3x3), t+center, rotated PSF offsets, psf weights.
#define SLICE_SHARED_DECL \
    __shared__ float sR[9]; __shared__ float st[3]; \
    __shared__ float sox[KK]; __shared__ float soy[KK]; __shared__ float soz[KK]; \
    __shared__ float spsf[KK];

__device__ __forceinline__ void slice_setup(const float* __restrict__ theta,
                                            const float* __restrict__ psf, int n,
                                            float* sR, float* st,
                                            float* sox, float* soy, float* soz,
                                            float* spsf) {
    int tid = threadIdx.x;
    if (tid < 9)       sR[tid]    = theta[n*12 + (tid/3)*4 + (tid%3)];
    else if (tid < 12) st[tid-9]  = theta[n*12 + (tid-9)*4 + 3] + 63.5f;
    __syncthreads();
    if (tid < KK) {
        float ox = (float)(tid % 3) - 1.f;
        float oy = (float)((tid / 3) % 3) - 1.f;
        float oz = (float)(tid / 9) - 1.f;
        sox[tid] = sR[0]*ox + sR[1]*oy + sR[2]*oz;
        soy[tid] = sR[3]*ox + sR[4]*oy + sR[5]*oz;
        soz[tid] = sR[6]*ox + sR[7]*oy + sR[8]*oz;
        spsf[tid] = psf[tid];
    }
    __syncthreads();
}

// ---------------------------------------------------------------------------
// A: PSF-weighted trilinear gather vol -> slices. Also accumulates ||s||^2
// (== p^T AtA p when vol==p) into ssq.
__global__ void A_kernel(const float* __restrict__ theta, const float* __restrict__ psf,
                         const float* __restrict__ vol, float* __restrict__ sout,
                         double* __restrict__ ssq) {
    SLICE_SHARED_DECL
    const int n = blockIdx.y;
    slice_setup(theta, psf, n, sR, st, sox, soy, soz, spsf);

    int pix = blockIdx.x * blockDim.x + threadIdx.x;
    int iw = pix & (WS - 1);
    int ih = pix >> 7;
    float fu = ((float)iw - 63.5f) * 1.5f;
    float fv = ((float)ih - 63.5f) * 1.5f;
    float qx = sR[0]*fu + sR[1]*fv + st[0];
    float qy = sR[3]*fu + sR[4]*fv + st[1];
    float qz = sR[6]*fu + sR[7]*fv + st[2];

    float acc = 0.f;
    for (int k = 0; k < KK; k++) {
        float px = qx + sox[k], py = qy + soy[k], pz = qz + soz[k];
        float xf = floorf(px), yf = floorf(py), zf = floorf(pz);
        int ix = (int)xf, iy = (int)yf, iz = (int)zf;
        float fx = px - xf, fy = py - yf, fz = pz - zf;
        float val;
        if (((unsigned)ix < Wv-1u) && ((unsigned)iy < Hv-1u) && ((unsigned)iz < Dv-1u)) {
            const float* b0 = vol + ((iz*Hv + iy)*Wv + ix);
            float v000 = __ldg(b0),        v001 = __ldg(b0+1);
            float v010 = __ldg(b0+Wv),     v011 = __ldg(b0+Wv+1);
            float v100 = __ldg(b0+HW),     v101 = __ldg(b0+HW+1);
            float v110 = __ldg(b0+HW+Wv),  v111 = __ldg(b0+HW+Wv+1);
            float c00 = v000 + fx*(v001 - v000);
            float c01 = v010 + fx*(v011 - v010);
            float c10 = v100 + fx*(v101 - v100);
            float c11 = v110 + fx*(v111 - v110);
            float c0 = c00 + fy*(c01 - c00);
            float c1 = c10 + fy*(c11 - c10);
            val = c0 + fz*(c1 - c0);
        } else {
            float wx[2] = {1.f - fx, fx}, wy[2] = {1.f - fy, fy}, wz[2] = {1.f - fz, fz};
            val = 0.f;
            #pragma unroll
            for (int dz = 0; dz < 2; dz++)
            #pragma unroll
            for (int dy = 0; dy < 2; dy++)
            #pragma unroll
            for (int dx = 0; dx < 2; dx++) {
                int xx = ix + dx, yy = iy + dy, zz = iz + dz;
                if (((unsigned)xx < (unsigned)Wv) && ((unsigned)yy < (unsigned)Hv) &&
                    ((unsigned)zz < (unsigned)Dv))
                    val += wx[dx]*wy[dy]*wz[dz]*__ldg(vol + ((zz*Hv + yy)*Wv + xx));
            }
        }
        acc += spsf[k] * val;
    }
    sout[n*(HS*WS) + pix] = acc;
    block_reduce_add((double)acc * (double)acc, ssq);
}

// ---------------------------------------------------------------------------
// At: PSF-weighted trilinear scatter-add of scale*slices -> dst (in place).
// scale = sign * (num/den) if num != nullptr else sign.
__global__ void At_kernel(const float* __restrict__ theta, const float* __restrict__ psf,
                          const float* __restrict__ sl, float* __restrict__ dst,
                          const double* __restrict__ num, const double* __restrict__ den,
                          float sign) {
    SLICE_SHARED_DECL
    __shared__ float sscale;
    if (threadIdx.x == 0)
        sscale = num ? sign * (float)(num[0] / den[0]) : sign;
    const int n = blockIdx.y;
    slice_setup(theta, psf, n, sR, st, sox, soy, soz, spsf);

    int pix = blockIdx.x * blockDim.x + threadIdx.x;
    int iw = pix & (WS - 1);
    int ih = pix >> 7;
    float fu = ((float)iw - 63.5f) * 1.5f;
    float fv = ((float)ih - 63.5f) * 1.5f;
    float qx = sR[0]*fu + sR[1]*fv + st[0];
    float qy = sR[3]*fu + sR[4]*fv + st[1];
    float qz = sR[6]*fu + sR[7]*fv + st[2];
    float v = sl[n*(HS*WS) + pix] * sscale;

    for (int k = 0; k < KK; k++) {
        float wv = v * spsf[k];
        float px = qx + sox[k], py = qy + soy[k], pz = qz + soz[k];
        float xf = floorf(px), yf = floorf(py), zf = floorf(pz);
        int ix = (int)xf, iy = (int)yf, iz = (int)zf;
        float fx = px - xf, fy = py - yf, fz = pz - zf;
        if (((unsigned)ix < Wv-1u) && ((unsigned)iy < Hv-1u) && ((unsigned)iz < Dv-1u)) {
            float* b0 = dst + ((iz*Hv + iy)*Wv + ix);
            float wx1 = fx, wx0 = 1.f - fx;
            float wy0 = 1.f - fy, wy1 = fy;
            float wz0 = 1.f - fz, wz1 = fz;
            float w00 = wy0*wz0*wv, w10 = wy1*wz0*wv;
            float w01 = wy0*wz1*wv, w11 = wy1*wz1*wv;
            atomicAdd(b0,         wx0*w00); atomicAdd(b0+1,        wx1*w00);
            atomicAdd(b0+Wv,      wx0*w10); atomicAdd(b0+Wv+1,     wx1*w10);
            atomicAdd(b0+HW,      wx0*w01); atomicAdd(b0+HW+1,     wx1*w01);
            atomicAdd(b0+HW+Wv,   wx0*w11); atomicAdd(b0+HW+Wv+1,  wx1*w11);
        } else {
            float wx[2] = {1.f - fx, fx}, wy[2] = {1.f - fy, fy}, wz[2] = {1.f - fz, fz};
            #pragma unroll
            for (int dz = 0; dz < 2; dz++)
            #pragma unroll
            for (int dy = 0; dy < 2; dy++)
            #pragma unroll
            for (int dx = 0; dx < 2; dx++) {
                int xx = ix + dx, yy = iy + dy, zz = iz + dz;
                if (((unsigned)xx < (unsigned)Wv) && ((unsigned)yy < (unsigned)Hv) &&
                    ((unsigned)zz < (unsigned)Dv))
                    atomicAdd(dst + ((zz*Hv + yy)*Wv + xx), wx[dx]*wy[dy]*wz[dz]*wv);
            }
        }
    }
}

// ---------------------------------------------------------------------------
// p = r (copy); rr0 += ||r||^2
__global__ void init_pr_kernel(const float4* __restrict__ r, float4* __restrict__ p,
                               double* __restrict__ rr) {
    int i = blockIdx.x * blockDim.x + threadIdx.x;
    float4 rv = r[i];
    p[i] = rv;
    double s = (double)rv.x*rv.x + (double)rv.y*rv.y + (double)rv.z*rv.z + (double)rv.w*rv.w;
    block_reduce_add(s, rr);
}

// rr += ||r||^2
__global__ void rr_kernel(const float4* __restrict__ r, double* __restrict__ rr) {
    int i = blockIdx.x * blockDim.x + threadIdx.x;
    float4 rv = r[i];
    double s = (double)rv.x*rv.x + (double)rv.y*rv.y + (double)rv.z*rv.z + (double)rv.w*rv.w;
    block_reduce_add(s, rr);
}

// x += alpha*p; p = r + beta*p   (alpha = rr_old/pAp, beta = rr_new/rr_old)
__global__ void pxu_kernel(float4* __restrict__ x, float4* __restrict__ p,
                           const float4* __restrict__ r,
                           const double* __restrict__ rr_old, const double* __restrict__ pAp,
                           const double* __restrict__ rr_new) {
    int i = blockIdx.x * blockDim.x + threadIdx.x;
    float alpha = (float)(*rr_old / *pAp);
    float beta  = (float)(*rr_new / *rr_old);
    float4 xv = x[i], pv = p[i], rv = r[i];
    xv.x += alpha*pv.x; xv.y += alpha*pv.y; xv.z += alpha*pv.z; xv.w += alpha*pv.w;
    x[i] = xv;
    pv.x = rv.x + beta*pv.x; pv.y = rv.y + beta*pv.y;
    pv.z = rv.z + beta*pv.z; pv.w = rv.w + beta*pv.w;
    p[i] = pv;
}

// out = relu(x + alpha*p)   (final iteration: r/p updates are dead)
__global__ void final_kernel(const float4* __restrict__ x, const float4* __restrict__ p,
                             const double* __restrict__ rr_old, const double* __restrict__ pAp,
                             float4* __restrict__ out) {
    int i = blockIdx.x * blockDim.x + threadIdx.x;
    float alpha = (float)(*rr_old / *pAp);
    float4 xv = x[i], pv = p[i];
    out[i] = make_float4(fmaxf(xv.x + alpha*pv.x, 0.f),
                         fmaxf(xv.y + alpha*pv.y, 0.f),
                         fmaxf(xv.z + alpha*pv.z, 0.f),
                         fmaxf(xv.w + alpha*pv.w, 0.f));
}

// ---------------------------------------------------------------------------
extern "C" void kernel_launch(void* const* d_in, const int* in_sizes, int n_in,
                              void* d_out, int out_size) {
    (void)in_sizes; (void)n_in; (void)out_size;
    const float* theta  = (const float*)d_in[0];
    const float* slices = (const float*)d_in[1];
    const float* volume = (const float*)d_in[2];
    const float* psf    = (const float*)d_in[3];
    float* out = (float*)d_out;

    void *vx, *vr, *vp, *vs, *vsc;
    cudaGetSymbolAddress(&vx, g_x);
    cudaGetSymbolAddress(&vr, g_r);
    cudaGetSymbolAddress(&vp, g_p);
    cudaGetSymbolAddress(&vs, g_s);
    cudaGetSymbolAddress(&vsc, g_scal);
    float *gx = (float*)vx, *gr = (float*)vr, *gp = (float*)vp, *gs = (float*)vs;
    double* gsc = (double*)vsc;

    const dim3 gridS(HS*WS/256, NS);
    const int vgrid = VOLN/4/256;

    cudaMemsetAsync(gsc, 0, 64*sizeof(double), 0);
    cudaMemsetAsync(gr, 0, VOLN*sizeof(float), 0);
    cudaMemcpyAsync(gx, volume, VOLN*sizeof(float), cudaMemcpyDeviceToDevice, 0);

    // r = b = At(slices)
    At_kernel<<<gridS, 256>>>(theta, psf, slices, gr, nullptr, nullptr, 1.f);
    // r -= AtA(x0)
    A_kernel<<<gridS, 256>>>(theta, psf, gx, gs, gsc + 63);
    At_kernel<<<gridS, 256>>>(theta, psf, gs, gr, nullptr, nullptr, -1.f);
    // p = r; rr0 = ||r||^2
    init_pr_kernel<<<vgrid, 256>>>((const float4*)gr, (float4*)gp, gsc + 0);

    for (int i = 0; i < NITER; i++) {
        // s = A(p), pAp_i = ||s||^2 (AtA symmetry)
        A_kernel<<<gridS, 256>>>(theta, psf, gp, gs, gsc + 32 + i);
        if (i < NITER - 1) {
            // r -= alpha * At(s), alpha = rr_i / pAp_i
            At_kernel<<<gridS, 256>>>(theta, psf, gs, gr, gsc + i, gsc + 32 + i, -1.f);
            // rr_{i+1} = ||r||^2
            rr_kernel<<<vgrid, 256>>>((const float4*)gr, gsc + i + 1);
            // x += alpha*p; p = r + beta*p
            pxu_kernel<<<vgrid, 256>>>((float4*)gx, (float4*)gp, (const float4*)gr,
                                       gsc + i, gsc + 32 + i, gsc + i + 1);
        } else {
            // out = relu(x + alpha*p); r/p updates dead on the last iteration
            final_kernel<<<vgrid, 256>>>((const float4*)gx, (const float4*)gp,
                                         gsc + i, gsc + 32 + i, (float4*)out);
        }
    }
}

// round 4
// speedup vs baseline: 1.2608x; 1.2517x over previous
#include <cuda_runtime.h>

#define Dv 128
#define Hv 128
#define Wv 128
#define NS 16
#define HS 128
#define WS 128
#define KK 27
#define NITER 10
#define VOLN (Dv*Hv*Wv)
#define HW (Hv*Wv)

// ---- scratch (no allocations allowed) ----
__device__ float g_x[VOLN];
__device__ float g_r[VOLN];
__device__ float g_p[VOLN];
__device__ float g_Apv[VOLN];
__device__ double g_scal[64];   // [0..10]=rr_i, [32..41]=pAp_i, [63]=dummy

// ---------------------------------------------------------------------------
__device__ __forceinline__ void block_reduce_add(double v, double* target) {
    #pragma unroll
    for (int o = 16; o > 0; o >>= 1) v += __shfl_down_sync(0xffffffffu, v, o);
    __shared__ double sm[32];
    int lane = threadIdx.x & 31, w = threadIdx.x >> 5;
    if (lane == 0) sm[w] = v;
    __syncthreads();
    if (w == 0) {
        v = (lane < (int)(blockDim.x >> 5)) ? sm[lane] : 0.0;
        #pragma unroll
        for (int o = 16; o > 0; o >>= 1) v += __shfl_down_sync(0xffffffffu, v, o);
        if (lane == 0) atomicAdd(target, v);
    }
}

#define SLICE_SHARED_DECL \
    __shared__ float sR[9]; __shared__ float st[3]; \
    __shared__ float sox[KK]; __shared__ float soy[KK]; __shared__ float soz[KK]; \
    __shared__ float spsf[KK];

__device__ __forceinline__ void slice_setup(const float* __restrict__ theta,
                                            const float* __restrict__ psf, int n,
                                            float* sR, float* st,
                                            float* sox, float* soy, float* soz,
                                            float* spsf) {
    int tid = threadIdx.x;
    if (tid < 9)       sR[tid]    = theta[n*12 + (tid/3)*4 + (tid%3)];
    else if (tid < 12) st[tid-9]  = theta[n*12 + (tid-9)*4 + 3] + 63.5f;
    __syncthreads();
    if (tid < KK) {
        float ox = (float)(tid % 3) - 1.f;
        float oy = (float)((tid / 3) % 3) - 1.f;
        float oz = (float)(tid / 9) - 1.f;
        sox[tid] = sR[0]*ox + sR[1]*oy + sR[2]*oz;
        soy[tid] = sR[3]*ox + sR[4]*oy + sR[5]*oz;
        soz[tid] = sR[6]*ox + sR[7]*oy + sR[8]*oz;
        spsf[tid] = psf[tid];
    }
    __syncthreads();
}

// per-pixel base point in volume coords
#define PIXEL_POINT() \
    int pix = blockIdx.x * blockDim.x + threadIdx.x; \
    int iw = pix & (WS - 1); \
    int ih = pix >> 7; \
    float fu = ((float)iw - 63.5f) * 1.5f; \
    float fv = ((float)ih - 63.5f) * 1.5f; \
    float qx = sR[0]*fu + sR[1]*fv + st[0]; \
    float qy = sR[3]*fu + sR[4]*fv + st[1]; \
    float qz = sR[6]*fu + sR[7]*fv + st[2];

// one trilinear gather tap
__device__ __forceinline__ float gather_tap(const float* __restrict__ vol,
                                            float px, float py, float pz) {
    float xf = floorf(px), yf = floorf(py), zf = floorf(pz);
    int ix = (int)xf, iy = (int)yf, iz = (int)zf;
    float fx = px - xf, fy = py - yf, fz = pz - zf;
    if (((unsigned)ix < Wv-1u) && ((unsigned)iy < Hv-1u) && ((unsigned)iz < Dv-1u)) {
        const float* b0 = vol + ((iz*Hv + iy)*Wv + ix);
        float v000 = __ldg(b0),        v001 = __ldg(b0+1);
        float v010 = __ldg(b0+Wv),     v011 = __ldg(b0+Wv+1);
        float v100 = __ldg(b0+HW),     v101 = __ldg(b0+HW+1);
        float v110 = __ldg(b0+HW+Wv),  v111 = __ldg(b0+HW+Wv+1);
        float c00 = v000 + fx*(v001 - v000);
        float c01 = v010 + fx*(v011 - v010);
        float c10 = v100 + fx*(v101 - v100);
        float c11 = v110 + fx*(v111 - v110);
        float c0 = c00 + fy*(c01 - c00);
        float c1 = c10 + fy*(c11 - c10);
        return c0 + fz*(c1 - c0);
    }
    float wx[2] = {1.f - fx, fx}, wy[2] = {1.f - fy, fy}, wz[2] = {1.f - fz, fz};
    float val = 0.f;
    #pragma unroll
    for (int dz = 0; dz < 2; dz++)
    #pragma unroll
    for (int dy = 0; dy < 2; dy++)
    #pragma unroll
    for (int dx = 0; dx < 2; dx++) {
        int xx = ix + dx, yy = iy + dy, zz = iz + dz;
        if (((unsigned)xx < (unsigned)Wv) && ((unsigned)yy < (unsigned)Hv) &&
            ((unsigned)zz < (unsigned)Dv))
            val += wx[dx]*wy[dy]*wz[dz]*__ldg(vol + ((zz*Hv + yy)*Wv + xx));
    }
    return val;
}

// one trilinear scatter tap (atomic)
__device__ __forceinline__ void scatter_tap(float* __restrict__ dst,
                                            float px, float py, float pz, float wv) {
    float xf = floorf(px), yf = floorf(py), zf = floorf(pz);
    int ix = (int)xf, iy = (int)yf, iz = (int)zf;
    float fx = px - xf, fy = py - yf, fz = pz - zf;
    if (((unsigned)ix < Wv-1u) && ((unsigned)iy < Hv-1u) && ((unsigned)iz < Dv-1u)) {
        float* b0 = dst + ((iz*Hv + iy)*Wv + ix);
        float wx1 = fx, wx0 = 1.f - fx;
        float w00 = (1.f-fy)*(1.f-fz)*wv, w10 = fy*(1.f-fz)*wv;
        float w01 = (1.f-fy)*fz*wv,       w11 = fy*fz*wv;
        atomicAdd(b0,         wx0*w00); atomicAdd(b0+1,        wx1*w00);
        atomicAdd(b0+Wv,      wx0*w10); atomicAdd(b0+Wv+1,     wx1*w10);
        atomicAdd(b0+HW,      wx0*w01); atomicAdd(b0+HW+1,     wx1*w01);
        atomicAdd(b0+HW+Wv,   wx0*w11); atomicAdd(b0+HW+Wv+1,  wx1*w11);
    } else {
        float wx[2] = {1.f - fx, fx}, wy[2] = {1.f - fy, fy}, wz[2] = {1.f - fz, fz};
        #pragma unroll
        for (int dz = 0; dz < 2; dz++)
        #pragma unroll
        for (int dy = 0; dy < 2; dy++)
        #pragma unroll
        for (int dx = 0; dx < 2; dx++) {
            int xx = ix + dx, yy = iy + dy, zz = iz + dz;
            if (((unsigned)xx < (unsigned)Wv) && ((unsigned)yy < (unsigned)Hv) &&
                ((unsigned)zz < (unsigned)Dv))
                atomicAdd(dst + ((zz*Hv + yy)*Wv + xx), wx[dx]*wy[dy]*wz[dz]*wv);
        }
    }
}

// ---------------------------------------------------------------------------
// At: scatter-add slices -> dst (dst pre-zeroed)
__global__ void At_kernel(const float* __restrict__ theta, const float* __restrict__ psf,
                          const float* __restrict__ sl, float* __restrict__ dst) {
    SLICE_SHARED_DECL
    const int n = blockIdx.y;
    slice_setup(theta, psf, n, sR, st, sox, soy, soz, spsf);
    PIXEL_POINT()
    float v = sl[n*(HS*WS) + pix];
    for (int k = 0; k < KK; k++)
        scatter_tap(dst, qx + sox[k], qy + soy[k], qz + soz[k], v * spsf[k]);
}

// Fused AtA: acc = (A vol_in)[pixel]; ssq += acc^2; scatter acc*psf back into vol_out.
__global__ void AtA_kernel(const float* __restrict__ theta, const float* __restrict__ psf,
                           const float* __restrict__ vol_in, float* __restrict__ vol_out,
                           double* __restrict__ ssq) {
    SLICE_SHARED_DECL
    const int n = blockIdx.y;
    slice_setup(theta, psf, n, sR, st, sox, soy, soz, spsf);
    PIXEL_POINT()
    float acc = 0.f;
    for (int k = 0; k < KK; k++)
        acc += spsf[k] * gather_tap(vol_in, qx + sox[k], qy + soy[k], qz + soz[k]);
    block_reduce_add((double)acc * (double)acc, ssq);
    for (int k = 0; k < KK; k++)
        scatter_tap(vol_out, qx + sox[k], qy + soy[k], qz + soz[k], acc * spsf[k]);
}

// Gather-only: ssq += ||A vol||^2  (last CG iteration needs only pAp)
__global__ void A_norm_kernel(const float* __restrict__ theta, const float* __restrict__ psf,
                              const float* __restrict__ vol, double* __restrict__ ssq) {
    SLICE_SHARED_DECL
    const int n = blockIdx.y;
    slice_setup(theta, psf, n, sR, st, sox, soy, soz, spsf);
    PIXEL_POINT()
    float acc = 0.f;
    for (int k = 0; k < KK; k++)
        acc += spsf[k] * gather_tap(vol, qx + sox[k], qy + soy[k], qz + soz[k]);
    block_reduce_add((double)acc * (double)acc, ssq);
}

// ---------------------------------------------------------------------------
#define VPT 4   // float4s per thread in streaming kernels
#define SGRID (VOLN/4/VPT/256)

// r = r - Apv; p = r; rr0 += ||r||^2   (r holds b on entry)
__global__ void init_pr_kernel(float4* __restrict__ r, const float4* __restrict__ Apv,
                               float4* __restrict__ p, double* __restrict__ rr) {
    int i0 = (blockIdx.x * blockDim.x + threadIdx.x) * VPT;
    double s = 0.0;
    #pragma unroll
    for (int j = 0; j < VPT; j++) {
        int i = i0 + j;
        float4 rv = r[i], av = Apv[i];
        rv.x -= av.x; rv.y -= av.y; rv.z -= av.z; rv.w -= av.w;
        r[i] = rv; p[i] = rv;
        s += (double)rv.x*rv.x + (double)rv.y*rv.y + (double)rv.z*rv.z + (double)rv.w*rv.w;
    }
    block_reduce_add(s, rr);
}

// r -= alpha*Apv (alpha = rr_old/pAp); rr_new += ||r||^2
__global__ void upd_r_rr_kernel(float4* __restrict__ r, const float4* __restrict__ Apv,
                                const double* __restrict__ rr_old, const double* __restrict__ pAp,
                                double* __restrict__ rr_new) {
    float alpha = (float)(*rr_old / *pAp);
    int i0 = (blockIdx.x * blockDim.x + threadIdx.x) * VPT;
    double s = 0.0;
    #pragma unroll
    for (int j = 0; j < VPT; j++) {
        int i = i0 + j;
        float4 rv = r[i], av = Apv[i];
        rv.x -= alpha*av.x; rv.y -= alpha*av.y; rv.z -= alpha*av.z; rv.w -= alpha*av.w;
        r[i] = rv;
        s += (double)rv.x*rv.x + (double)rv.y*rv.y + (double)rv.z*rv.z + (double)rv.w*rv.w;
    }
    block_reduce_add(s, rr_new);
}

// x += alpha*p; p = r + beta*p
__global__ void pxu_kernel(float4* __restrict__ x, float4* __restrict__ p,
                           const float4* __restrict__ r,
                           const double* __restrict__ rr_old, const double* __restrict__ pAp,
                           const double* __restrict__ rr_new) {
    float alpha = (float)(*rr_old / *pAp);
    float beta  = (float)(*rr_new / *rr_old);
    int i0 = (blockIdx.x * blockDim.x + threadIdx.x) * VPT;
    #pragma unroll
    for (int j = 0; j < VPT; j++) {
        int i = i0 + j;
        float4 xv = x[i], pv = p[i], rv = r[i];
        xv.x += alpha*pv.x; xv.y += alpha*pv.y; xv.z += alpha*pv.z; xv.w += alpha*pv.w;
        x[i] = xv;
        pv.x = rv.x + beta*pv.x; pv.y = rv.y + beta*pv.y;
        pv.z = rv.z + beta*pv.z; pv.w = rv.w + beta*pv.w;
        p[i] = pv;
    }
}

// out = relu(x + alpha*p)
__global__ void final_kernel(const float4* __restrict__ x, const float4* __restrict__ p,
                             const double* __restrict__ rr_old, const double* __restrict__ pAp,
                             float4* __restrict__ out) {
    float alpha = (float)(*rr_old / *pAp);
    int i0 = (blockIdx.x * blockDim.x + threadIdx.x) * VPT;
    #pragma unroll
    for (int j = 0; j < VPT; j++) {
        int i = i0 + j;
        float4 xv = x[i], pv = p[i];
        out[i] = make_float4(fmaxf(xv.x + alpha*pv.x, 0.f),
                             fmaxf(xv.y + alpha*pv.y, 0.f),
                             fmaxf(xv.z + alpha*pv.z, 0.f),
                             fmaxf(xv.w + alpha*pv.w, 0.f));
    }
}

// ---------------------------------------------------------------------------
extern "C" void kernel_launch(void* const* d_in, const int* in_sizes, int n_in,
                              void* d_out, int out_size) {
    (void)in_sizes; (void)n_in; (void)out_size;
    const float* theta  = (const float*)d_in[0];
    const float* slices = (const float*)d_in[1];
    const float* volume = (const float*)d_in[2];
    const float* psf    = (const float*)d_in[3];
    float* out = (float*)d_out;

    void *vx, *vr, *vp, *vApv, *vsc;
    cudaGetSymbolAddress(&vx, g_x);
    cudaGetSymbolAddress(&vr, g_r);
    cudaGetSymbolAddress(&vp, g_p);
    cudaGetSymbolAddress(&vApv, g_Apv);
    cudaGetSymbolAddress(&vsc, g_scal);
    float *gx = (float*)vx, *gr = (float*)vr, *gp = (float*)vp, *gApv = (float*)vApv;
    double* gsc = (double*)vsc;

    const dim3 gridS(HS*WS/256, NS);

    cudaMemsetAsync(gsc, 0, 64*sizeof(double), 0);
    cudaMemsetAsync(gr, 0, VOLN*sizeof(float), 0);
    cudaMemsetAsync(gApv, 0, VOLN*sizeof(float), 0);
    cudaMemcpyAsync(gx, volume, VOLN*sizeof(float), cudaMemcpyDeviceToDevice, 0);

    // r = b = At(slices);  Apv = AtA(x0)
    At_kernel<<<gridS, 256>>>(theta, psf, slices, gr);
    AtA_kernel<<<gridS, 256>>>(theta, psf, gx, gApv, gsc + 63);
    // r = b - Apv; p = r; rr0
    init_pr_kernel<<<SGRID, 256>>>((float4*)gr, (const float4*)gApv, (float4*)gp, gsc + 0);

    for (int i = 0; i < NITER - 1; i++) {
        cudaMemsetAsync(gApv, 0, VOLN*sizeof(float), 0);
        // Apv = AtA(p); pAp_i = ||A p||^2
        AtA_kernel<<<gridS, 256>>>(theta, psf, gp, gApv, gsc + 32 + i);
        // r -= alpha*Apv; rr_{i+1}
        upd_r_rr_kernel<<<SGRID, 256>>>((float4*)gr, (const float4*)gApv,
                                        gsc + i, gsc + 32 + i, gsc + i + 1);
        // x += alpha*p; p = r + beta*p
        pxu_kernel<<<SGRID, 256>>>((float4*)gx, (float4*)gp, (const float4*)gr,
                                   gsc + i, gsc + 32 + i, gsc + i + 1);
    }
    // last iteration: only pAp_9 and x-update matter
    A_norm_kernel<<<gridS, 256>>>(theta, psf, gp, gsc + 32 + NITER - 1);
    final_kernel<<<SGRID, 256>>>((const float4*)gx, (const float4*)gp,
                                 gsc + NITER - 1, gsc + 32 + NITER - 1, (float4*)out);
}